// round 4
// baseline (speedup 1.0000x reference)
#include <cuda_runtime.h>
#include <math.h>

// ---------------------------------------------------------------------------
// RefEncoder: 4x stride-2 3x3 convs (SAME pad = 0 before / 1 after), gelu(tanh)
// on first three, then per-group query proj + codebook-key proj + argmax.
// Shapes: x[16,3,256,256] -> [16,64,128,128] -> [16,128,64,64] -> [16,256,32,32]
//         -> latent[16,256,16,16] -> code uint8 [16,16,16,4], plus [h,w]=[256,256]
// ---------------------------------------------------------------------------

#define NIMG 16

// scratch (device globals: allocation-free per harness rules)
__device__ float g_buf1[NIMG * 64 * 128 * 128];   // conv1 out (gelu)
__device__ float g_buf2[NIMG * 128 * 64 * 64];    // conv2 out (gelu)
__device__ float g_buf3[NIMG * 256 * 32 * 32];    // conv3 out (gelu)
__device__ float g_buf4[NIMG * 256 * 16 * 16];    // conv4 out (latent)
__device__ float g_kproj[4 * 256 * 64];           // kproj[m][k][c]

__device__ __forceinline__ float gelu_tanh(float x) {
    // jax.nn.gelu approximate=True
    float x3 = x * x * x;
    float t = tanhf(0.7978845608028654f * (x + 0.044715f * x3));
    return 0.5f * x * (1.0f + t);
}

// ---------------------------------------------------------------------------
// conv1: Cin=3, Cout=64, 256 -> 128, normalize input (2x-1), gelu output.
// Block: 256 threads, tile = 64 oc x 8x8 spatial. 16 outputs/thread.
// ---------------------------------------------------------------------------
__global__ __launch_bounds__(256) void conv1_kernel(
    const float* __restrict__ x, const float* __restrict__ w,
    const float* __restrict__ b)
{
    const int HIN = 256, HOUT = 128;
    __shared__ float sIn[3][17][18];
    __shared__ __align__(16) float sW[3][9][64];

    int n = blockIdx.z;
    int tiles_x = HOUT / 8;                 // 16
    int ty = blockIdx.x / tiles_x;
    int txo = blockIdx.x % tiles_x;
    int oy0 = ty * 8, ox0 = txo * 8;
    int tid = threadIdx.x;

    // weights: 64*3*9 = 1728, coalesced read, store [ic][kk][oc]
    for (int idx = tid; idx < 1728; idx += 256) {
        int oc = idx / 27, r = idx % 27;
        int ic = r / 9, kk = r % 9;
        sW[ic][kk][oc] = w[idx];
    }
    // input patch 3*17*17, normalized 2x-1 (== (x-0.5)/0.5 exactly)
    for (int idx = tid; idx < 3 * 17 * 17; idx += 256) {
        int ic = idx / 289, r2 = idx % 289;
        int r = r2 / 17, c = r2 % 17;
        int iy = oy0 * 2 + r, ix = ox0 * 2 + c;
        float v = 0.0f;
        if (iy < HIN && ix < HIN)
            v = 2.0f * x[((n * 3 + ic) * HIN + iy) * HIN + ix] - 1.0f;
        sIn[ic][r][c] = v;
    }
    __syncthreads();

    int ocq = (tid & 15) * 4;
    int sp = (tid >> 4) * 4;
    int oy = sp >> 3, oxl = sp & 7;

    float acc[4][4];
#pragma unroll
    for (int j = 0; j < 4; j++)
#pragma unroll
        for (int q = 0; q < 4; q++) acc[j][q] = 0.0f;

#pragma unroll
    for (int ic = 0; ic < 3; ic++) {
#pragma unroll
        for (int kk = 0; kk < 9; kk++) {
            float4 wv = *(const float4*)&sW[ic][kk][ocq];
#pragma unroll
            for (int j = 0; j < 4; j++) {
                float iv = sIn[ic][oy * 2 + kk / 3][(oxl + j) * 2 + kk % 3];
                acc[j][0] = fmaf(iv, wv.x, acc[j][0]);
                acc[j][1] = fmaf(iv, wv.y, acc[j][1]);
                acc[j][2] = fmaf(iv, wv.z, acc[j][2]);
                acc[j][3] = fmaf(iv, wv.w, acc[j][3]);
            }
        }
    }
#pragma unroll
    for (int j = 0; j < 4; j++)
#pragma unroll
        for (int q = 0; q < 4; q++) {
            int oc = ocq + q;
            float v = acc[j][q] + b[oc];
            g_buf1[((n * 64 + oc) * HOUT + oy0 + oy) * HOUT + ox0 + oxl + j] =
                gelu_tanh(v);
        }
}

// ---------------------------------------------------------------------------
// generic stride-2 3x3 conv, ic-chunked by 8. Tile: 64 oc x 8x8 spatial.
// ---------------------------------------------------------------------------
template <int CIN, int COUT, int HIN, int HOUT, bool DO_GELU>
__global__ __launch_bounds__(256) void conv_kernel(
    const float* __restrict__ in, const float* __restrict__ w,
    const float* __restrict__ b, float* __restrict__ out)
{
    __shared__ float sIn[8][17][18];
    __shared__ __align__(16) float sW[8][9][64];

    int n = blockIdx.z;
    int oc0 = blockIdx.y * 64;
    const int tiles_x = HOUT / 8;
    int ty = blockIdx.x / tiles_x;
    int txo = blockIdx.x % tiles_x;
    int oy0 = ty * 8, ox0 = txo * 8;
    int tid = threadIdx.x;

    int ocq = (tid & 15) * 4;
    int sp = (tid >> 4) * 4;
    int oy = sp >> 3, oxl = sp & 7;

    float acc[4][4];
#pragma unroll
    for (int j = 0; j < 4; j++)
#pragma unroll
        for (int q = 0; q < 4; q++) acc[j][q] = 0.0f;

    for (int ic0 = 0; ic0 < CIN; ic0 += 8) {
        __syncthreads();
        // weights chunk: 64 oc * 8 ic * 9 = 4608, store [ic][kk][oc]
        for (int idx = tid; idx < 4608; idx += 256) {
            int oc = idx / 72, r = idx % 72;
            int ic = r / 9, kk = r % 9;
            sW[ic][kk][oc] = w[(oc0 + oc) * (CIN * 9) + (ic0 + ic) * 9 + kk];
        }
        // input patch chunk: 8 * 17 * 17 = 2312
        for (int idx = tid; idx < 2312; idx += 256) {
            int ic = idx / 289, r2 = idx % 289;
            int r = r2 / 17, c = r2 % 17;
            int iy = oy0 * 2 + r, ix = ox0 * 2 + c;
            float v = 0.0f;
            if (iy < HIN && ix < HIN)
                v = in[((n * CIN + ic0 + ic) * HIN + iy) * HIN + ix];
            sIn[ic][r][c] = v;
        }
        __syncthreads();

#pragma unroll
        for (int ic = 0; ic < 8; ic++) {
#pragma unroll
            for (int kk = 0; kk < 9; kk++) {
                float4 wv = *(const float4*)&sW[ic][kk][ocq];
#pragma unroll
                for (int j = 0; j < 4; j++) {
                    float iv = sIn[ic][oy * 2 + kk / 3][(oxl + j) * 2 + kk % 3];
                    acc[j][0] = fmaf(iv, wv.x, acc[j][0]);
                    acc[j][1] = fmaf(iv, wv.y, acc[j][1]);
                    acc[j][2] = fmaf(iv, wv.z, acc[j][2]);
                    acc[j][3] = fmaf(iv, wv.w, acc[j][3]);
                }
            }
        }
    }

#pragma unroll
    for (int j = 0; j < 4; j++)
#pragma unroll
        for (int q = 0; q < 4; q++) {
            int oc = oc0 + ocq + q;
            float v = acc[j][q] + b[oc];
            if (DO_GELU) v = gelu_tanh(v);
            out[((n * COUT + oc) * HOUT + oy0 + oy) * HOUT + ox0 + oxl + j] = v;
        }
}

// ---------------------------------------------------------------------------
// kproj[m][k][c] = sum_d codebook[m][k][d] * wk[m][c][d]
// ---------------------------------------------------------------------------
__global__ __launch_bounds__(256) void kproj_kernel(
    const float* __restrict__ codebook, const float* __restrict__ wk)
{
    int idx = blockIdx.x * 256 + threadIdx.x;   // 65536 total
    int c = idx & 63;
    int k = (idx >> 6) & 255;
    int m = idx >> 14;
    const float* cb = codebook + (m * 256 + k) * 64;
    const float* wkp = wk + (m * 64 + c) * 64;
    float s = 0.0f;
#pragma unroll
    for (int d = 0; d < 64; d++) s = fmaf(cb[d], wkp[d], s);
    g_kproj[idx] = s;
}

// ---------------------------------------------------------------------------
// score + argmax. One block per (n,y,x). 256 threads = 4 groups x 64.
// mode 0: uint8 codes (+optional int32 hw at hw_ptr)
// mode 1: int32 codes + int32 hw
// mode 2: float32 codes + float32 hw   (outputs cast to common float buffer)
// ---------------------------------------------------------------------------
__global__ __launch_bounds__(256) void score_kernel(
    const float* __restrict__ wq, unsigned char* __restrict__ out_raw,
    int mode, int has_hw)
{
    __shared__ float q[256];
    __shared__ float qp[256];
    __shared__ float redV[256];
    __shared__ int redI[256];

    int bid = blockIdx.x;                       // n*256 + y*16 + x
    int n = bid >> 8;
    int y = (bid >> 4) & 15;
    int xp = bid & 15;
    int t = threadIdx.x;

    q[t] = g_buf4[((n * 256 + t) * 16 + y) * 16 + xp];
    __syncthreads();

    int m = t >> 6, c = t & 63;
    {
        const float* wqp = wq + (m * 64 + c) * 64;
        const float* qg = q + m * 64;
        float s = 0.0f;
#pragma unroll
        for (int d = 0; d < 64; d++) s = fmaf(qg[d], wqp[d], s);
        qp[t] = s;
    }
    __syncthreads();

    float best = -3.402823466e38f;
    int bi = 0;
    const float* qpm = qp + m * 64;
#pragma unroll
    for (int kk = 0; kk < 4; kk++) {
        int k = c * 4 + kk;                     // ascending k per thread
        const float* kpp = g_kproj + (m * 256 + k) * 64;
        float sc = 0.0f;
#pragma unroll
        for (int d = 0; d < 64; d++) sc = fmaf(qpm[d], kpp[d], sc);
        if (sc > best) { best = sc; bi = k; }   // strict > keeps first max
    }
    redV[t] = best;
    redI[t] = bi;
    __syncthreads();

    // per-group (64-thread) reduction; smaller k wins on exact tie
    for (int off = 32; off >= 1; off >>= 1) {
        if (c < off) {
            float ov = redV[t + off];
            int oi = redI[t + off];
            if (ov > redV[t] || (ov == redV[t] && oi < redI[t])) {
                redV[t] = ov;
                redI[t] = oi;
            }
        }
        __syncthreads();
    }

    if (c == 0) {
        int k = redI[t];
        int oidx = bid * 4 + m;                 // [n][y][x][m]
        if (mode == 0)      ((unsigned char*)out_raw)[oidx] = (unsigned char)k;
        else if (mode == 1) ((int*)out_raw)[oidx] = k;
        else                ((float*)out_raw)[oidx] = (float)k;
    }
    if (bid == 0 && t == 0 && has_hw) {
        if (mode == 0) {
            int* hw = (int*)(out_raw + 16384);
            hw[0] = 256; hw[1] = 256;
        } else if (mode == 1) {
            int* hw = (int*)out_raw;
            hw[16384] = 256; hw[16385] = 256;
        } else {
            float* hw = (float*)out_raw;
            hw[16384] = 256.0f; hw[16385] = 256.0f;
        }
    }
}

// ---------------------------------------------------------------------------
// launch
// ---------------------------------------------------------------------------
extern "C" void kernel_launch(void* const* d_in, const int* in_sizes, int n_in,
                              void* d_out, int out_size)
{
    // ---- defensive input remap by element count (handles reordered inputs) --
    // expected: x=3145728 w1=1728 b1=64 w2=73728 b2=128 w3=294912 b3=256
    //           w4=589824 b4=256 codebook=65536 wq=16384 wk=16384
    int ix = 0, iw1 = 1, ib1 = 2, iw2 = 3, ib2 = 4, iw3 = 5, ib3 = 6,
        iw4 = 7, ib4 = 8, icb = 9, iwq = 10, iwk = 11;
    if (n_in == 12) {
        int p256[2] = {-1, -1}, np256 = 0;
        int p16k[2] = {-1, -1}, np16k = 0;
        int xpos = -1;
        for (int i = 0; i < 12; i++) {
            switch (in_sizes[i]) {
                case 3145728: ix = i; xpos = i; break;
                case 1728:    iw1 = i; break;
                case 64:      ib1 = i; break;
                case 73728:   iw2 = i; break;
                case 128:     ib2 = i; break;
                case 294912:  iw3 = i; break;
                case 589824:  iw4 = i; break;
                case 65536:   icb = i; break;
                case 256:     if (np256 < 2) p256[np256++] = i; break;
                case 16384:   if (np16k < 2) p16k[np16k++] = i; break;
                default: break;
            }
        }
        if (np256 == 2) { ib3 = p256[0]; ib4 = p256[1]; }   // both are zeros
        if (np16k == 2) {
            // declaration order (x first) => wq before wk; otherwise
            // (e.g. alphabetical, x last) => wk before wq.
            if (xpos >= 0 && xpos < p16k[0]) { iwq = p16k[0]; iwk = p16k[1]; }
            else                             { iwk = p16k[0]; iwq = p16k[1]; }
        }
    }

    const float* x        = (const float*)d_in[ix];
    const float* w1       = (const float*)d_in[iw1];
    const float* b1       = (const float*)d_in[ib1];
    const float* w2       = (const float*)d_in[iw2];
    const float* b2       = (const float*)d_in[ib2];
    const float* w3       = (const float*)d_in[iw3];
    const float* b3       = (const float*)d_in[ib3];
    const float* w4       = (const float*)d_in[iw4];
    const float* b4       = (const float*)d_in[ib4];
    const float* codebook = (const float*)d_in[icb];
    const float* wq       = (const float*)d_in[iwq];
    const float* wk       = (const float*)d_in[iwk];

    float *buf1, *buf2, *buf3, *buf4;
    cudaGetSymbolAddress((void**)&buf1, g_buf1);
    cudaGetSymbolAddress((void**)&buf2, g_buf2);
    cudaGetSymbolAddress((void**)&buf3, g_buf3);
    cudaGetSymbolAddress((void**)&buf4, g_buf4);

    // conv1: 256 spatial tiles x 16 images
    conv1_kernel<<<dim3(256, 1, NIMG), 256>>>(x, w1, b1);
    // conv2: 64->128ch, 128->64
    conv_kernel<64, 128, 128, 64, true>
        <<<dim3(64, 2, NIMG), 256>>>(buf1, w2, b2, buf2);
    // conv3: 128->256ch, 64->32
    conv_kernel<128, 256, 64, 32, true>
        <<<dim3(16, 4, NIMG), 256>>>(buf2, w3, b3, buf3);
    // conv4: 256->256ch, 32->16 (no gelu)
    conv_kernel<256, 256, 32, 16, false>
        <<<dim3(4, 4, NIMG), 256>>>(buf3, w4, b4, buf4);
    // kproj
    kproj_kernel<<<256, 256>>>(codebook, wk);

    // Output layout:
    //   out_size == 16386 -> outputs cast to one float32 buffer (codes + h,w)
    //   out_size == 16384 -> uint8 codes only
    //   out_size >= 16392 -> uint8 codes followed by int32 h,w (byte layout)
    int mode, has_hw;
    if (out_size == 16386)      { mode = 2; has_hw = 1; }
    else if (out_size >= 16392) { mode = 0; has_hw = 1; }
    else                        { mode = 0; has_hw = 0; }

    score_kernel<<<4096, 256>>>(wq, (unsigned char*)d_out, mode, has_hw);
}

// round 5
// speedup vs baseline: 2.0300x; 2.0300x over previous
#include <cuda_runtime.h>
#include <math.h>

// ---------------------------------------------------------------------------
// RefEncoder: 4x stride-2 3x3 convs (SAME pad = 0 before / 1 after), gelu(tanh)
// on first three, then per-group query proj + codebook-key proj + argmax.
// ---------------------------------------------------------------------------

#define NIMG 16

__device__ float g_buf1[NIMG * 64 * 128 * 128];   // conv1 out (gelu)
__device__ float g_buf2[NIMG * 128 * 64 * 64];    // conv2 out (gelu)
__device__ float g_buf3[NIMG * 256 * 32 * 32];    // conv3 out (gelu)
__device__ float g_buf4[NIMG * 256 * 16 * 16];    // conv4 out (latent)
__device__ float g_kprojT[4 * 64 * 256];          // kproj transposed [m][c][k]

__device__ __forceinline__ float gelu_tanh(float x) {
    float x3 = x * x * x;
    float t = tanhf(0.7978845608028654f * (x + 0.044715f * x3));
    return 0.5f * x * (1.0f + t);
}

// ---------------------------------------------------------------------------
// conv1: Cin=3, Cout=64, 256 -> 128, normalize input (2x-1), gelu output.
// ---------------------------------------------------------------------------
__global__ __launch_bounds__(256) void conv1_kernel(
    const float* __restrict__ x, const float* __restrict__ w,
    const float* __restrict__ b)
{
    const int HIN = 256, HOUT = 128;
    __shared__ float sIn[3][17][18];
    __shared__ __align__(16) float sW[3][9][64];

    int n = blockIdx.z;
    int tiles_x = HOUT / 8;
    int ty = blockIdx.x / tiles_x;
    int txo = blockIdx.x % tiles_x;
    int oy0 = ty * 8, ox0 = txo * 8;
    int tid = threadIdx.x;

    for (int idx = tid; idx < 1728; idx += 256) {
        int oc = idx / 27, r = idx % 27;
        int ic = r / 9, kk = r % 9;
        sW[ic][kk][oc] = w[idx];
    }
    for (int idx = tid; idx < 3 * 17 * 17; idx += 256) {
        int ic = idx / 289, r2 = idx % 289;
        int r = r2 / 17, c = r2 % 17;
        int iy = oy0 * 2 + r, ix = ox0 * 2 + c;
        float v = 0.0f;
        if (iy < HIN && ix < HIN)
            v = 2.0f * x[((n * 3 + ic) * HIN + iy) * HIN + ix] - 1.0f;
        sIn[ic][r][c] = v;
    }
    __syncthreads();

    int ocq = (tid & 15) * 4;
    int sp = (tid >> 4) * 4;
    int oy = sp >> 3, oxl = sp & 7;

    float acc[4][4];
#pragma unroll
    for (int j = 0; j < 4; j++)
#pragma unroll
        for (int q = 0; q < 4; q++) acc[j][q] = 0.0f;

#pragma unroll
    for (int ic = 0; ic < 3; ic++) {
#pragma unroll
        for (int kk = 0; kk < 9; kk++) {
            float4 wv = *(const float4*)&sW[ic][kk][ocq];
#pragma unroll
            for (int j = 0; j < 4; j++) {
                float iv = sIn[ic][oy * 2 + kk / 3][(oxl + j) * 2 + kk % 3];
                acc[j][0] = fmaf(iv, wv.x, acc[j][0]);
                acc[j][1] = fmaf(iv, wv.y, acc[j][1]);
                acc[j][2] = fmaf(iv, wv.z, acc[j][2]);
                acc[j][3] = fmaf(iv, wv.w, acc[j][3]);
            }
        }
    }
#pragma unroll
    for (int j = 0; j < 4; j++)
#pragma unroll
        for (int q = 0; q < 4; q++) {
            int oc = ocq + q;
            float v = acc[j][q] + b[oc];
            g_buf1[((n * 64 + oc) * HOUT + oy0 + oy) * HOUT + ox0 + oxl + j] =
                gelu_tanh(v);
        }
}

// ---------------------------------------------------------------------------
// conv v1 (4oc x 4px, 8x8 tile): used for conv4 (preserves exact fp order).
// ---------------------------------------------------------------------------
template <int CIN, int COUT, int HIN, int HOUT, bool DO_GELU>
__global__ __launch_bounds__(256) void conv_kernel(
    const float* __restrict__ in, const float* __restrict__ w,
    const float* __restrict__ b, float* __restrict__ out)
{
    __shared__ float sIn[8][17][18];
    __shared__ __align__(16) float sW[8][9][64];

    int n = blockIdx.z;
    int oc0 = blockIdx.y * 64;
    const int tiles_x = HOUT / 8;
    int ty = blockIdx.x / tiles_x;
    int txo = blockIdx.x % tiles_x;
    int oy0 = ty * 8, ox0 = txo * 8;
    int tid = threadIdx.x;

    int ocq = (tid & 15) * 4;
    int sp = (tid >> 4) * 4;
    int oy = sp >> 3, oxl = sp & 7;

    float acc[4][4];
#pragma unroll
    for (int j = 0; j < 4; j++)
#pragma unroll
        for (int q = 0; q < 4; q++) acc[j][q] = 0.0f;

    for (int ic0 = 0; ic0 < CIN; ic0 += 8) {
        __syncthreads();
        for (int idx = tid; idx < 4608; idx += 256) {
            int oc = idx / 72, r = idx % 72;
            int ic = r / 9, kk = r % 9;
            sW[ic][kk][oc] = w[(oc0 + oc) * (CIN * 9) + (ic0 + ic) * 9 + kk];
        }
        for (int idx = tid; idx < 2312; idx += 256) {
            int ic = idx / 289, r2 = idx % 289;
            int r = r2 / 17, c = r2 % 17;
            int iy = oy0 * 2 + r, ix = ox0 * 2 + c;
            float v = 0.0f;
            if (iy < HIN && ix < HIN)
                v = in[((n * CIN + ic0 + ic) * HIN + iy) * HIN + ix];
            sIn[ic][r][c] = v;
        }
        __syncthreads();

#pragma unroll
        for (int ic = 0; ic < 8; ic++) {
#pragma unroll
            for (int kk = 0; kk < 9; kk++) {
                float4 wv = *(const float4*)&sW[ic][kk][ocq];
#pragma unroll
                for (int j = 0; j < 4; j++) {
                    float iv = sIn[ic][oy * 2 + kk / 3][(oxl + j) * 2 + kk % 3];
                    acc[j][0] = fmaf(iv, wv.x, acc[j][0]);
                    acc[j][1] = fmaf(iv, wv.y, acc[j][1]);
                    acc[j][2] = fmaf(iv, wv.z, acc[j][2]);
                    acc[j][3] = fmaf(iv, wv.w, acc[j][3]);
                }
            }
        }
    }

#pragma unroll
    for (int j = 0; j < 4; j++)
#pragma unroll
        for (int q = 0; q < 4; q++) {
            int oc = oc0 + ocq + q;
            float v = acc[j][q] + b[oc];
            if (DO_GELU) v = gelu_tanh(v);
            out[((n * COUT + oc) * HOUT + oy0 + oy) * HOUT + ox0 + oxl + j] = v;
        }
}

// ---------------------------------------------------------------------------
// conv v2 (4oc x 8px, 8x16 tile): halves weight-LDS per FMA, doubles ILP.
// Same per-output accumulation order as v1 (ic0 chunks, ic, kk ascending).
// Used for conv2 / conv3.
// ---------------------------------------------------------------------------
template <int CIN, int COUT, int HIN, int HOUT, bool DO_GELU>
__global__ __launch_bounds__(256) void conv8_kernel(
    const float* __restrict__ in, const float* __restrict__ w,
    const float* __restrict__ b, float* __restrict__ out)
{
    __shared__ float sIn[8][17][34];                 // rows 17, cols 33 (+pad)
    __shared__ __align__(16) float sW[8][9][64];

    int n = blockIdx.z;
    int oc0 = blockIdx.y * 64;
    const int tiles_x = HOUT / 16;
    int ty = blockIdx.x / tiles_x;
    int txo = blockIdx.x % tiles_x;
    int oy0 = ty * 8, ox0 = txo * 16;
    int tid = threadIdx.x;

    int ocq = (tid & 15) * 4;
    int sp = tid >> 4;                               // 0..15
    int oy = sp >> 1;                                // 0..7
    int ox8 = (sp & 1) * 8;                          // 0 or 8

    float acc[8][4];
#pragma unroll
    for (int j = 0; j < 8; j++)
#pragma unroll
        for (int q = 0; q < 4; q++) acc[j][q] = 0.0f;

    for (int ic0 = 0; ic0 < CIN; ic0 += 8) {
        __syncthreads();
        for (int idx = tid; idx < 4608; idx += 256) {
            int oc = idx / 72, r = idx % 72;
            int ic = r / 9, kk = r % 9;
            sW[ic][kk][oc] = w[(oc0 + oc) * (CIN * 9) + (ic0 + ic) * 9 + kk];
        }
        // input patch: 8 ic x 17 rows x 33 cols
        for (int idx = tid; idx < 8 * 17 * 33; idx += 256) {
            int ic = idx / 561;
            int rem = idx - ic * 561;
            int r = rem / 33, c = rem - r * 33;
            int iy = oy0 * 2 + r, ix = ox0 * 2 + c;
            float v = 0.0f;
            if (iy < HIN && ix < HIN)
                v = in[((n * CIN + ic0 + ic) * HIN + iy) * HIN + ix];
            sIn[ic][r][c] = v;
        }
        __syncthreads();

#pragma unroll
        for (int ic = 0; ic < 8; ic++) {
#pragma unroll
            for (int kk = 0; kk < 9; kk++) {
                float4 wv = *(const float4*)&sW[ic][kk][ocq];
                const float* row = &sIn[ic][oy * 2 + kk / 3][kk % 3];
#pragma unroll
                for (int j = 0; j < 8; j++) {
                    float iv = row[(ox8 + j) * 2];
                    acc[j][0] = fmaf(iv, wv.x, acc[j][0]);
                    acc[j][1] = fmaf(iv, wv.y, acc[j][1]);
                    acc[j][2] = fmaf(iv, wv.z, acc[j][2]);
                    acc[j][3] = fmaf(iv, wv.w, acc[j][3]);
                }
            }
        }
    }

#pragma unroll
    for (int j = 0; j < 8; j++)
#pragma unroll
        for (int q = 0; q < 4; q++) {
            int oc = oc0 + ocq + q;
            float v = acc[j][q] + b[oc];
            if (DO_GELU) v = gelu_tanh(v);
            out[((n * COUT + oc) * HOUT + oy0 + oy) * HOUT + ox0 + ox8 + j] = v;
        }
}

// ---------------------------------------------------------------------------
// kproj: kprojT[m][c][k] = sum_d codebook[m][k][d] * wk[m][c][d]  (transposed)
// ---------------------------------------------------------------------------
__global__ __launch_bounds__(256) void kproj_kernel(
    const float* __restrict__ codebook, const float* __restrict__ wk)
{
    int idx = blockIdx.x * 256 + threadIdx.x;   // 65536 total
    int c = idx & 63;
    int k = (idx >> 6) & 255;
    int m = idx >> 14;
    const float* cb = codebook + (m * 256 + k) * 64;
    const float* wkp = wk + (m * 64 + c) * 64;
    float s = 0.0f;
#pragma unroll
    for (int d = 0; d < 64; d++) s = fmaf(cb[d], wkp[d], s);
    g_kprojT[(m * 64 + c) * 256 + k] = s;
}

// ---------------------------------------------------------------------------
// score v2: grid (pxtile=8, m=4, n=16) = 512 blocks, 256 threads.
// Per block: 32 px, one m. q & wq staged in smem, qp in smem, kproj read
// as uniform float4 LDG from transposed layout (L1-resident).
// Same fp accumulation order as the passing v1 (sequential d / c loops).
// ---------------------------------------------------------------------------
__global__ __launch_bounds__(256) void score2_kernel(
    const float* __restrict__ wq, unsigned char* __restrict__ out_raw,
    int mode, int has_hw)
{
    __shared__ float qsT[64 * 36];      // [d][px]  (pad 36)
    __shared__ float qpT[64 * 36];      // [c][px]
    __shared__ float wqs[64 * 65];      // [c][d]   (pad 65)

    int t = threadIdx.x;
    int pt = blockIdx.x;                // 0..7 px tiles of 32
    int m = blockIdx.y;
    int n = blockIdx.z;

    for (int idx = t; idx < 64 * 32; idx += 256) {
        int d = idx >> 5, px = idx & 31;
        qsT[d * 36 + px] = g_buf4[(n * 256 + m * 64 + d) * 256 + pt * 32 + px];
    }
    for (int idx = t; idx < 4096; idx += 256) {
        int c = idx >> 6, d = idx & 63;
        wqs[c * 65 + d] = wq[(m * 64 + c) * 64 + d];
    }
    __syncthreads();

    // qp[c][px] = sum_d q[px][d] * wq[m][c][d]  (d ascending, fmaf chain)
    {
        int c = t & 63, pxg = t >> 6;   // 4 groups of 8 px
        float a0 = 0, a1 = 0, a2 = 0, a3 = 0, a4 = 0, a5 = 0, a6 = 0, a7 = 0;
#pragma unroll 8
        for (int d = 0; d < 64; d++) {
            float wv = wqs[c * 65 + d];
            const float* qr = &qsT[d * 36 + pxg * 8];
            float4 qa = *(const float4*)qr;
            float4 qb = *(const float4*)(qr + 4);
            a0 = fmaf(wv, qa.x, a0); a1 = fmaf(wv, qa.y, a1);
            a2 = fmaf(wv, qa.z, a2); a3 = fmaf(wv, qa.w, a3);
            a4 = fmaf(wv, qb.x, a4); a5 = fmaf(wv, qb.y, a5);
            a6 = fmaf(wv, qb.z, a6); a7 = fmaf(wv, qb.w, a7);
        }
        float* qo = &qpT[c * 36 + pxg * 8];
        qo[0] = a0; qo[1] = a1; qo[2] = a2; qo[3] = a3;
        qo[4] = a4; qo[5] = a5; qo[6] = a6; qo[7] = a7;
    }
    __syncthreads();

    // scores: thread = 1 px x 32 k; c ascending (same order as v1's d loop)
    int px = t & 31, kgrp = t >> 5;     // 8 groups x 32 k
    int k0 = kgrp * 32;
    float acc[32];
#pragma unroll
    for (int k = 0; k < 32; k++) acc[k] = 0.0f;

    const float* kbase = g_kprojT + (m * 64) * 256 + k0;
    for (int c = 0; c < 64; c++) {
        float qv = qpT[c * 36 + px];
        const float4* kr = (const float4*)(kbase + c * 256);
#pragma unroll
        for (int v = 0; v < 8; v++) {
            float4 kv = __ldg(kr + v);
            acc[v * 4 + 0] = fmaf(qv, kv.x, acc[v * 4 + 0]);
            acc[v * 4 + 1] = fmaf(qv, kv.y, acc[v * 4 + 1]);
            acc[v * 4 + 2] = fmaf(qv, kv.z, acc[v * 4 + 2]);
            acc[v * 4 + 3] = fmaf(qv, kv.w, acc[v * 4 + 3]);
        }
    }

    float best = -3.402823466e38f;
    int bi = 0;
#pragma unroll
    for (int k = 0; k < 32; k++)
        if (acc[k] > best) { best = acc[k]; bi = k0 + k; }  // strict > = first max

    __syncthreads();                     // qsT free; overlay reduction arrays
    float* redV = qsT;
    int* redI = (int*)(qsT + 256);
    redV[t] = best;
    redI[t] = bi;
    __syncthreads();

    if (t < 32) {
        float bv = redV[t];
        int bx = redI[t];
#pragma unroll
        for (int g = 1; g < 8; g++) {
            float v = redV[g * 32 + t];
            int i2 = redI[g * 32 + t];
            if (v > bv || (v == bv && i2 < bx)) { bv = v; bx = i2; }
        }
        int oidx = (n * 256 + pt * 32 + t) * 4 + m;
        if (mode == 0)      ((unsigned char*)out_raw)[oidx] = (unsigned char)bx;
        else if (mode == 1) ((int*)out_raw)[oidx] = bx;
        else                ((float*)out_raw)[oidx] = (float)bx;
    }
    if (blockIdx.x == 0 && blockIdx.y == 0 && blockIdx.z == 0 && t == 0 && has_hw) {
        if (mode == 0) {
            int* hw = (int*)(out_raw + 16384);
            hw[0] = 256; hw[1] = 256;
        } else if (mode == 1) {
            int* hw = (int*)out_raw;
            hw[16384] = 256; hw[16385] = 256;
        } else {
            float* hw = (float*)out_raw;
            hw[16384] = 256.0f; hw[16385] = 256.0f;
        }
    }
}

// ---------------------------------------------------------------------------
// launch
// ---------------------------------------------------------------------------
extern "C" void kernel_launch(void* const* d_in, const int* in_sizes, int n_in,
                              void* d_out, int out_size)
{
    // defensive input remap by element count
    int ix = 0, iw1 = 1, ib1 = 2, iw2 = 3, ib2 = 4, iw3 = 5, ib3 = 6,
        iw4 = 7, ib4 = 8, icb = 9, iwq = 10, iwk = 11;
    if (n_in == 12) {
        int p256[2] = {-1, -1}, np256 = 0;
        int p16k[2] = {-1, -1}, np16k = 0;
        int xpos = -1;
        for (int i = 0; i < 12; i++) {
            switch (in_sizes[i]) {
                case 3145728: ix = i; xpos = i; break;
                case 1728:    iw1 = i; break;
                case 64:      ib1 = i; break;
                case 73728:   iw2 = i; break;
                case 128:     ib2 = i; break;
                case 294912:  iw3 = i; break;
                case 589824:  iw4 = i; break;
                case 65536:   icb = i; break;
                case 256:     if (np256 < 2) p256[np256++] = i; break;
                case 16384:   if (np16k < 2) p16k[np16k++] = i; break;
                default: break;
            }
        }
        if (np256 == 2) { ib3 = p256[0]; ib4 = p256[1]; }
        if (np16k == 2) {
            if (xpos >= 0 && xpos < p16k[0]) { iwq = p16k[0]; iwk = p16k[1]; }
            else                             { iwk = p16k[0]; iwq = p16k[1]; }
        }
    }

    const float* x        = (const float*)d_in[ix];
    const float* w1       = (const float*)d_in[iw1];
    const float* b1       = (const float*)d_in[ib1];
    const float* w2       = (const float*)d_in[iw2];
    const float* b2       = (const float*)d_in[ib2];
    const float* w3       = (const float*)d_in[iw3];
    const float* b3       = (const float*)d_in[ib3];
    const float* w4       = (const float*)d_in[iw4];
    const float* b4       = (const float*)d_in[ib4];
    const float* codebook = (const float*)d_in[icb];
    const float* wq       = (const float*)d_in[iwq];
    const float* wk       = (const float*)d_in[iwk];

    float *buf1, *buf2, *buf3, *buf4;
    cudaGetSymbolAddress((void**)&buf1, g_buf1);
    cudaGetSymbolAddress((void**)&buf2, g_buf2);
    cudaGetSymbolAddress((void**)&buf3, g_buf3);
    cudaGetSymbolAddress((void**)&buf4, g_buf4);

    // conv1: 256 tiles x 16 images
    conv1_kernel<<<dim3(256, 1, NIMG), 256>>>(x, w1, b1);
    // conv2: 64->128, 128->64; tiles 8y*4x=32, 2 oc tiles -> 1024 blocks
    conv8_kernel<64, 128, 128, 64, true>
        <<<dim3(32, 2, NIMG), 256>>>(buf1, w2, b2, buf2);
    // conv3: 128->256, 64->32; tiles 4y*2x=8, 4 oc tiles -> 512 blocks
    conv8_kernel<128, 256, 64, 32, true>
        <<<dim3(8, 4, NIMG), 256>>>(buf2, w3, b3, buf3);
    // conv4: 256->256, 32->16 (no gelu), v1 kernel (exact fp order preserved)
    conv_kernel<256, 256, 32, 16, false>
        <<<dim3(4, 4, NIMG), 256>>>(buf3, w4, b4, buf4);
    // kproj (transposed output)
    kproj_kernel<<<256, 256>>>(codebook, wk);

    int mode, has_hw;
    if (out_size == 16386)      { mode = 2; has_hw = 1; }
    else if (out_size >= 16392) { mode = 0; has_hw = 1; }
    else                        { mode = 0; has_hw = 0; }

    score2_kernel<<<dim3(8, 4, NIMG), 256>>>(wq, (unsigned char*)d_out,
                                             mode, has_hw);
}

// round 6
// speedup vs baseline: 2.0505x; 1.0101x over previous
#include <cuda_runtime.h>
#include <math.h>

// ---------------------------------------------------------------------------
// RefEncoder: 4x stride-2 3x3 convs (SAME pad = 0 before / 1 after), gelu(tanh)
// on first three, then per-group query proj + codebook-key proj + argmax.
// ---------------------------------------------------------------------------

#define NIMG 16

__device__ float g_buf1[NIMG * 64 * 128 * 128];   // conv1 out (gelu)
__device__ float g_buf2[NIMG * 128 * 64 * 64];    // conv2 out (gelu)
__device__ float g_buf3[NIMG * 256 * 32 * 32];    // conv3 out (gelu)
__device__ float g_buf4[NIMG * 256 * 16 * 16];    // conv4 out (latent)
__device__ float g_kprojT[4 * 64 * 256];          // kproj transposed [m][c][k]

__device__ __forceinline__ float gelu_tanh(float x) {
    float x3 = x * x * x;
    float t = tanhf(0.7978845608028654f * (x + 0.044715f * x3));
    return 0.5f * x * (1.0f + t);
}

// ---------------------------------------------------------------------------
// conv1: Cin=3, Cout=64, 256 -> 128, normalize input (2x-1), gelu output.
// ---------------------------------------------------------------------------
__global__ __launch_bounds__(256) void conv1_kernel(
    const float* __restrict__ x, const float* __restrict__ w,
    const float* __restrict__ b)
{
    const int HIN = 256, HOUT = 128;
    __shared__ float sIn[3][17][18];
    __shared__ __align__(16) float sW[3][9][64];

    int n = blockIdx.z;
    int tiles_x = HOUT / 8;
    int ty = blockIdx.x / tiles_x;
    int txo = blockIdx.x % tiles_x;
    int oy0 = ty * 8, ox0 = txo * 8;
    int tid = threadIdx.x;

    for (int idx = tid; idx < 1728; idx += 256) {
        int oc = idx / 27, r = idx % 27;
        int ic = r / 9, kk = r % 9;
        sW[ic][kk][oc] = w[idx];
    }
    for (int idx = tid; idx < 3 * 17 * 17; idx += 256) {
        int ic = idx / 289, r2 = idx % 289;
        int r = r2 / 17, c = r2 % 17;
        int iy = oy0 * 2 + r, ix = ox0 * 2 + c;
        float v = 0.0f;
        if (iy < HIN && ix < HIN)
            v = 2.0f * x[((n * 3 + ic) * HIN + iy) * HIN + ix] - 1.0f;
        sIn[ic][r][c] = v;
    }
    __syncthreads();

    int ocq = (tid & 15) * 4;
    int sp = (tid >> 4) * 4;
    int oy = sp >> 3, oxl = sp & 7;

    float acc[4][4];
#pragma unroll
    for (int j = 0; j < 4; j++)
#pragma unroll
        for (int q = 0; q < 4; q++) acc[j][q] = 0.0f;

#pragma unroll
    for (int ic = 0; ic < 3; ic++) {
#pragma unroll
        for (int kk = 0; kk < 9; kk++) {
            float4 wv = *(const float4*)&sW[ic][kk][ocq];
#pragma unroll
            for (int j = 0; j < 4; j++) {
                float iv = sIn[ic][oy * 2 + kk / 3][(oxl + j) * 2 + kk % 3];
                acc[j][0] = fmaf(iv, wv.x, acc[j][0]);
                acc[j][1] = fmaf(iv, wv.y, acc[j][1]);
                acc[j][2] = fmaf(iv, wv.z, acc[j][2]);
                acc[j][3] = fmaf(iv, wv.w, acc[j][3]);
            }
        }
    }
#pragma unroll
    for (int j = 0; j < 4; j++)
#pragma unroll
        for (int q = 0; q < 4; q++) {
            int oc = ocq + q;
            float v = acc[j][q] + b[oc];
            g_buf1[((n * 64 + oc) * HOUT + oy0 + oy) * HOUT + ox0 + oxl + j] =
                gelu_tanh(v);
        }
}

// ---------------------------------------------------------------------------
// convR: register-blocked stride-2 3x3 conv.
// Tile: 64 oc x (8 rows x 16 cols) px. Thread: 4 oc x 8 px (one half-row).
// Inner loop over (ic, ky): load the 18 input cols this thread needs as
// 9 float2 into registers, reuse across kx=0,1,2 (kk = ky*3+kx ascending ->
// accumulation order bit-identical to the original ic/kk loop).
// Per (ic,ky): 9 LDS.64 + 3 LDS.128 = 120B for 96 fmaf (1.25 B/FMA).
// ---------------------------------------------------------------------------
template <int CIN, int COUT, int HIN, int HOUT, bool DO_GELU>
__global__ __launch_bounds__(256) void convR_kernel(
    const float* __restrict__ in, const float* __restrict__ w,
    const float* __restrict__ b, float* __restrict__ out)
{
    __shared__ __align__(16) float sIn[8][17][34];   // 33 cols used (+1 pad)
    __shared__ __align__(16) float sW[8][9][64];

    int n = blockIdx.z;
    int oc0 = blockIdx.y * 64;
    const int tiles_x = HOUT / 16;                   // >= 1
    int ty = (tiles_x > 1) ? (blockIdx.x / tiles_x) : blockIdx.x;
    int txo = (tiles_x > 1) ? (blockIdx.x % tiles_x) : 0;
    int oy0 = ty * 8, ox0 = txo * 16;
    int tid = threadIdx.x;

    int ocq = (tid & 15) * 4;
    int sp = tid >> 4;                               // 0..15
    int oy = sp >> 1;                                // 0..7
    int ox8 = (sp & 1) * 8;                          // 0 or 8

    float acc[8][4];
#pragma unroll
    for (int j = 0; j < 8; j++)
#pragma unroll
        for (int q = 0; q < 4; q++) acc[j][q] = 0.0f;

    for (int ic0 = 0; ic0 < CIN; ic0 += 8) {
        __syncthreads();
        // weights chunk: 64 oc * 8 ic * 9 = 4608, [ic][kk][oc]
        for (int idx = tid; idx < 4608; idx += 256) {
            int oc = idx / 72, r = idx % 72;
            int ic = r / 9, kk = r % 9;
            sW[ic][kk][oc] = w[(oc0 + oc) * (CIN * 9) + (ic0 + ic) * 9 + kk];
        }
        // input patch chunk: 8 ic x 17 rows x 33 cols
        for (int idx = tid; idx < 8 * 17 * 33; idx += 256) {
            int ic = idx / 561;
            int rem = idx - ic * 561;
            int r = rem / 33, c = rem - r * 33;
            int iy = oy0 * 2 + r, ix = ox0 * 2 + c;
            float v = 0.0f;
            if (iy < HIN && ix < HIN)
                v = in[((n * CIN + ic0 + ic) * HIN + iy) * HIN + ix];
            sIn[ic][r][c] = v;
        }
        __syncthreads();

#pragma unroll
        for (int ic = 0; ic < 8; ic++) {
#pragma unroll
            for (int ky = 0; ky < 3; ky++) {
                const float* row = &sIn[ic][oy * 2 + ky][2 * ox8];
                float2 rv[9];
#pragma unroll
                for (int i = 0; i < 9; i++)
                    rv[i] = *(const float2*)(row + 2 * i);
#pragma unroll
                for (int kx = 0; kx < 3; kx++) {
                    float4 wv = *(const float4*)&sW[ic][ky * 3 + kx][ocq];
#pragma unroll
                    for (int j = 0; j < 8; j++) {
                        float iv = (kx == 0) ? rv[j].x
                                 : (kx == 1) ? rv[j].y
                                             : rv[j + 1].x;
                        acc[j][0] = fmaf(iv, wv.x, acc[j][0]);
                        acc[j][1] = fmaf(iv, wv.y, acc[j][1]);
                        acc[j][2] = fmaf(iv, wv.z, acc[j][2]);
                        acc[j][3] = fmaf(iv, wv.w, acc[j][3]);
                    }
                }
            }
        }
    }

#pragma unroll
    for (int j = 0; j < 8; j++)
#pragma unroll
        for (int q = 0; q < 4; q++) {
            int oc = oc0 + ocq + q;
            float v = acc[j][q] + b[oc];
            if (DO_GELU) v = gelu_tanh(v);
            out[((n * COUT + oc) * HOUT + oy0 + oy) * HOUT + ox0 + ox8 + j] = v;
        }
}

// ---------------------------------------------------------------------------
// kproj: kprojT[m][c][k] = sum_d codebook[m][k][d] * wk[m][c][d]  (transposed)
// ---------------------------------------------------------------------------
__global__ __launch_bounds__(256) void kproj_kernel(
    const float* __restrict__ codebook, const float* __restrict__ wk)
{
    int idx = blockIdx.x * 256 + threadIdx.x;   // 65536 total
    int c = idx & 63;
    int k = (idx >> 6) & 255;
    int m = idx >> 14;
    const float* cb = codebook + (m * 256 + k) * 64;
    const float* wkp = wk + (m * 64 + c) * 64;
    float s = 0.0f;
#pragma unroll
    for (int d = 0; d < 64; d++) s = fmaf(cb[d], wkp[d], s);
    g_kprojT[(m * 64 + c) * 256 + k] = s;
}

// ---------------------------------------------------------------------------
// score v2: grid (pxtile=8, m=4, n=16) = 512 blocks, 256 threads.
// ---------------------------------------------------------------------------
__global__ __launch_bounds__(256) void score2_kernel(
    const float* __restrict__ wq, unsigned char* __restrict__ out_raw,
    int mode, int has_hw)
{
    __shared__ float qsT[64 * 36];      // [d][px]  (pad 36)
    __shared__ float qpT[64 * 36];      // [c][px]
    __shared__ float wqs[64 * 65];      // [c][d]   (pad 65)

    int t = threadIdx.x;
    int pt = blockIdx.x;                // 0..7 px tiles of 32
    int m = blockIdx.y;
    int n = blockIdx.z;

    for (int idx = t; idx < 64 * 32; idx += 256) {
        int d = idx >> 5, px = idx & 31;
        qsT[d * 36 + px] = g_buf4[(n * 256 + m * 64 + d) * 256 + pt * 32 + px];
    }
    for (int idx = t; idx < 4096; idx += 256) {
        int c = idx >> 6, d = idx & 63;
        wqs[c * 65 + d] = wq[(m * 64 + c) * 64 + d];
    }
    __syncthreads();

    // qp[c][px] = sum_d q[px][d] * wq[m][c][d]  (d ascending, fmaf chain)
    {
        int c = t & 63, pxg = t >> 6;   // 4 groups of 8 px
        float a0 = 0, a1 = 0, a2 = 0, a3 = 0, a4 = 0, a5 = 0, a6 = 0, a7 = 0;
#pragma unroll 8
        for (int d = 0; d < 64; d++) {
            float wv = wqs[c * 65 + d];
            const float* qr = &qsT[d * 36 + pxg * 8];
            float4 qa = *(const float4*)qr;
            float4 qb = *(const float4*)(qr + 4);
            a0 = fmaf(wv, qa.x, a0); a1 = fmaf(wv, qa.y, a1);
            a2 = fmaf(wv, qa.z, a2); a3 = fmaf(wv, qa.w, a3);
            a4 = fmaf(wv, qb.x, a4); a5 = fmaf(wv, qb.y, a5);
            a6 = fmaf(wv, qb.z, a6); a7 = fmaf(wv, qb.w, a7);
        }
        float* qo = &qpT[c * 36 + pxg * 8];
        qo[0] = a0; qo[1] = a1; qo[2] = a2; qo[3] = a3;
        qo[4] = a4; qo[5] = a5; qo[6] = a6; qo[7] = a7;
    }
    __syncthreads();

    // scores: thread = 1 px x 32 k; c ascending
    int px = t & 31, kgrp = t >> 5;     // 8 groups x 32 k
    int k0 = kgrp * 32;
    float acc[32];
#pragma unroll
    for (int k = 0; k < 32; k++) acc[k] = 0.0f;

    const float* kbase = g_kprojT + (m * 64) * 256 + k0;
    for (int c = 0; c < 64; c++) {
        float qv = qpT[c * 36 + px];
        const float4* kr = (const float4*)(kbase + c * 256);
#pragma unroll
        for (int v = 0; v < 8; v++) {
            float4 kv = __ldg(kr + v);
            acc[v * 4 + 0] = fmaf(qv, kv.x, acc[v * 4 + 0]);
            acc[v * 4 + 1] = fmaf(qv, kv.y, acc[v * 4 + 1]);
            acc[v * 4 + 2] = fmaf(qv, kv.z, acc[v * 4 + 2]);
            acc[v * 4 + 3] = fmaf(qv, kv.w, acc[v * 4 + 3]);
        }
    }

    float best = -3.402823466e38f;
    int bi = 0;
#pragma unroll
    for (int k = 0; k < 32; k++)
        if (acc[k] > best) { best = acc[k]; bi = k0 + k; }  // strict > = first max

    __syncthreads();                     // qsT free; overlay reduction arrays
    float* redV = qsT;
    int* redI = (int*)(qsT + 256);
    redV[t] = best;
    redI[t] = bi;
    __syncthreads();

    if (t < 32) {
        float bv = redV[t];
        int bx = redI[t];
#pragma unroll
        for (int g = 1; g < 8; g++) {
            float v = redV[g * 32 + t];
            int i2 = redI[g * 32 + t];
            if (v > bv || (v == bv && i2 < bx)) { bv = v; bx = i2; }
        }
        int oidx = (n * 256 + pt * 32 + t) * 4 + m;
        if (mode == 0)      ((unsigned char*)out_raw)[oidx] = (unsigned char)bx;
        else if (mode == 1) ((int*)out_raw)[oidx] = bx;
        else                ((float*)out_raw)[oidx] = (float)bx;
    }
    if (blockIdx.x == 0 && blockIdx.y == 0 && blockIdx.z == 0 && t == 0 && has_hw) {
        if (mode == 0) {
            int* hw = (int*)(out_raw + 16384);
            hw[0] = 256; hw[1] = 256;
        } else if (mode == 1) {
            int* hw = (int*)out_raw;
            hw[16384] = 256; hw[16385] = 256;
        } else {
            float* hw = (float*)out_raw;
            hw[16384] = 256.0f; hw[16385] = 256.0f;
        }
    }
}

// ---------------------------------------------------------------------------
// launch
// ---------------------------------------------------------------------------
extern "C" void kernel_launch(void* const* d_in, const int* in_sizes, int n_in,
                              void* d_out, int out_size)
{
    // defensive input remap by element count
    int ix = 0, iw1 = 1, ib1 = 2, iw2 = 3, ib2 = 4, iw3 = 5, ib3 = 6,
        iw4 = 7, ib4 = 8, icb = 9, iwq = 10, iwk = 11;
    if (n_in == 12) {
        int p256[2] = {-1, -1}, np256 = 0;
        int p16k[2] = {-1, -1}, np16k = 0;
        int xpos = -1;
        for (int i = 0; i < 12; i++) {
            switch (in_sizes[i]) {
                case 3145728: ix = i; xpos = i; break;
                case 1728:    iw1 = i; break;
                case 64:      ib1 = i; break;
                case 73728:   iw2 = i; break;
                case 128:     ib2 = i; break;
                case 294912:  iw3 = i; break;
                case 589824:  iw4 = i; break;
                case 65536:   icb = i; break;
                case 256:     if (np256 < 2) p256[np256++] = i; break;
                case 16384:   if (np16k < 2) p16k[np16k++] = i; break;
                default: break;
            }
        }
        if (np256 == 2) { ib3 = p256[0]; ib4 = p256[1]; }
        if (np16k == 2) {
            if (xpos >= 0 && xpos < p16k[0]) { iwq = p16k[0]; iwk = p16k[1]; }
            else                             { iwk = p16k[0]; iwq = p16k[1]; }
        }
    }

    const float* x        = (const float*)d_in[ix];
    const float* w1       = (const float*)d_in[iw1];
    const float* b1       = (const float*)d_in[ib1];
    const float* w2       = (const float*)d_in[iw2];
    const float* b2       = (const float*)d_in[ib2];
    const float* w3       = (const float*)d_in[iw3];
    const float* b3       = (const float*)d_in[ib3];
    const float* w4       = (const float*)d_in[iw4];
    const float* b4       = (const float*)d_in[ib4];
    const float* codebook = (const float*)d_in[icb];
    const float* wq       = (const float*)d_in[iwq];
    const float* wk       = (const float*)d_in[iwk];

    float *buf1, *buf2, *buf3, *buf4;
    cudaGetSymbolAddress((void**)&buf1, g_buf1);
    cudaGetSymbolAddress((void**)&buf2, g_buf2);
    cudaGetSymbolAddress((void**)&buf3, g_buf3);
    cudaGetSymbolAddress((void**)&buf4, g_buf4);

    // conv1: 256 tiles x 16 images
    conv1_kernel<<<dim3(256, 1, NIMG), 256>>>(x, w1, b1);
    // conv2: 64->128, 128->64; (64/8)*(64/16)=32 tiles, 2 oc blocks
    convR_kernel<64, 128, 128, 64, true>
        <<<dim3(32, 2, NIMG), 256>>>(buf1, w2, b2, buf2);
    // conv3: 128->256, 64->32; (32/8)*(32/16)=8 tiles, 4 oc blocks
    convR_kernel<128, 256, 64, 32, true>
        <<<dim3(8, 4, NIMG), 256>>>(buf2, w3, b3, buf3);
    // conv4: 256->256, 32->16; (16/8)*(16/16)=2 tiles, 4 oc blocks
    convR_kernel<256, 256, 32, 16, false>
        <<<dim3(2, 4, NIMG), 256>>>(buf3, w4, b4, buf4);
    // kproj (transposed output)
    kproj_kernel<<<256, 256>>>(codebook, wk);

    int mode, has_hw;
    if (out_size == 16386)      { mode = 2; has_hw = 1; }
    else if (out_size >= 16392) { mode = 0; has_hw = 1; }
    else                        { mode = 0; has_hw = 0; }

    score2_kernel<<<dim3(8, 4, NIMG), 256>>>(wq, (unsigned char*)d_out,
                                             mode, has_hw);
}